// round 14
// baseline (speedup 1.0000x reference)
#include <cuda_runtime.h>
#include <cuda_fp16.h>
#include <cstdint>

// ---------------------------------------------------------------------------
// out = concat( relu(A@relu(A@F)), A@(A@NF) ), N=8192, D=E=64.
// Both layers: C[8192,128] = A[8192,8192] @ W[8192,128], relu on cols<64.
// Path: single-digit fp16 HMMA, cp.async 3-stage pipeline with BK=64 stages
// (2 x BK=32 sub-tiles per stage -> half the barriers), 256 threads,
// SPLIT-K=2 (fp32 partials + deterministic fixed-order reduce).
//   A pre-converted to fp16 (scaled by 2^13 -> [0,1), all normal).
//   C = (Ah@Bh) / 8192, fp32 accumulate.  Error ~2e-4 total (thresh 1e-3).
// ---------------------------------------------------------------------------

constexpr int NN  = 8192;
constexpr int WID = 128;
constexpr int KSPLIT = 2;
constexpr int KHALF  = NN / KSPLIT;           // 4096

// smem: fp16 rows of 32 elems (64B) at pitch 80B (conflict-free ldmatrix).
// One stage = two sub-tiles of [A 64x32 | B 128x32].
constexpr int PITCH    = 80;
constexpr int AH_OFF   = 0;                   // within sub-tile: 5120 B
constexpr int BH_OFF   = 5120;                // 10240 B
constexpr int SUB_BYTES = 15360;
constexpr int BUF_BYTES = 2 * SUB_BYTES;      // 30720 (BK=64 stage)
constexpr int NSTAGE   = 3;
constexpr int SMEM_GEMM = NSTAGE * BUF_BYTES; // 92160 -> 2 CTAs/SM

__device__ __align__(16) __half g_Ah[(size_t)NN * NN];      // A * 2^13, fp16
__device__ __align__(16) __half g_B1[(size_t)WID * NN];     // [n][k]
__device__ __align__(16) __half g_B2[(size_t)WID * NN];
__device__ __align__(16) float  g_part[(size_t)KSPLIT * NN * WID];

// ---------------------------------------------------------------------------
// helpers
// ---------------------------------------------------------------------------
__device__ __forceinline__ uint32_t s2u(const void* p) {
    uint32_t a;
    asm("{ .reg .u64 t; cvta.to.shared.u64 t, %1; cvt.u32.u64 %0, t; }"
        : "=r"(a) : "l"(p));
    return a;
}

__device__ __forceinline__ void ldmx4(uint32_t* r, uint32_t addr) {
    asm volatile("ldmatrix.sync.aligned.m8n8.x4.shared.b16 {%0,%1,%2,%3}, [%4];"
                 : "=r"(r[0]), "=r"(r[1]), "=r"(r[2]), "=r"(r[3]) : "r"(addr));
}

__device__ __forceinline__ void hmma(float* c, const uint32_t* a,
                                     const uint32_t* b) {
    asm volatile(
        "mma.sync.aligned.m16n8k16.row.col.f32.f16.f16.f32 "
        "{%0,%1,%2,%3}, {%4,%5,%6,%7}, {%8,%9}, {%0,%1,%2,%3};"
        : "+f"(c[0]), "+f"(c[1]), "+f"(c[2]), "+f"(c[3])
        : "r"(a[0]), "r"(a[1]), "r"(a[2]), "r"(a[3]), "r"(b[0]), "r"(b[1]));
}

__device__ __forceinline__ void cp16(uint32_t saddr, const void* gaddr) {
    asm volatile("cp.async.cg.shared.global [%0], [%1], 16;"
                 :: "r"(saddr), "l"(gaddr) : "memory");
}
#define CP_COMMIT() asm volatile("cp.async.commit_group;" ::: "memory")
#define CP_WAIT1()  asm volatile("cp.async.wait_group 1;" ::: "memory")

__device__ __forceinline__ uint32_t packh(__half a, __half b) {
    __half2 t = __halves2half2(a, b);
    return *reinterpret_cast<uint32_t*>(&t);
}

// ---------------------------------------------------------------------------
// conv_a: A fp32 -> fp16 * 2^13   (8 elems / thread)
// ---------------------------------------------------------------------------
__global__ __launch_bounds__(256) void conv_a(const float* __restrict__ A) {
    size_t i = (size_t)blockIdx.x * 256 + threadIdx.x;
    const float4* p = reinterpret_cast<const float4*>(A) + i * 2;
    float4 a = p[0], b = p[1];
    uint4 h = make_uint4(
        packh(__float2half_rn(a.x * 8192.0f), __float2half_rn(a.y * 8192.0f)),
        packh(__float2half_rn(a.z * 8192.0f), __float2half_rn(a.w * 8192.0f)),
        packh(__float2half_rn(b.x * 8192.0f), __float2half_rn(b.y * 8192.0f)),
        packh(__float2half_rn(b.z * 8192.0f), __float2half_rn(b.w * 8192.0f)));
    reinterpret_cast<uint4*>(g_Ah)[i] = h;
}

// ---------------------------------------------------------------------------
// conv_b1: transpose W=[F|NF] ([8192,64] each) -> g_B1 [n][k] fp16
// ---------------------------------------------------------------------------
__global__ void conv_b1(const float* __restrict__ F, const float* __restrict__ NF) {
    __shared__ float tile[32][33];
    int k0 = blockIdx.x * 32, n0 = blockIdx.y * 32;
    int tx = threadIdx.x, ty = threadIdx.y;              // (32, 8)
    const float* src = (n0 < 64) ? F : NF;
    int nc = (n0 < 64) ? n0 : (n0 - 64);
    #pragma unroll
    for (int j = 0; j < 4; ++j) {
        int r = ty + 8 * j;
        tile[r][tx] = src[(size_t)(k0 + r) * 64 + nc + tx];
    }
    __syncthreads();
    #pragma unroll
    for (int j = 0; j < 4; ++j) {
        int rn = ty + 8 * j;
        g_B1[(size_t)(n0 + rn) * NN + k0 + tx] = __float2half_rn(tile[tx][rn]);
    }
}

// ---------------------------------------------------------------------------
// one BK=32 sub-tile: 8 ldmx4 + 16 HMMA (warp tile 32x32, 8 warps = 2x4)
// ---------------------------------------------------------------------------
__device__ __forceinline__ void compute_sub(uint32_t base, uint32_t aLaneOff,
                                            uint32_t bLaneOff, int warp_m,
                                            int warp_n, float (&am)[2][4][4]) {
    const uint32_t aho = base + AH_OFF + warp_m * 2560 + aLaneOff;
    const uint32_t bho = base + BH_OFF + warp_n * 2560 + bLaneOff;
    #pragma unroll
    for (int ks = 0; ks < 2; ++ks) {
        uint32_t ah[2][4], bh[2][4];
        ldmx4(ah[0], aho + ks * 32);
        ldmx4(ah[1], aho + ks * 32 + 1280);
        ldmx4(bh[0], bho + ks * 32);
        ldmx4(bh[1], bho + ks * 32 + 1280);
        #pragma unroll
        for (int mt = 0; mt < 2; ++mt)
            #pragma unroll
            for (int nt = 0; nt < 4; ++nt)
                hmma(am[mt][nt], ah[mt], &bh[nt >> 1][(nt & 1) * 2]);
    }
}

// ---------------------------------------------------------------------------
// gemm_f16<LAYER>: partial[split] = A[:, kh] @ W[kh, :]  (fp32 partials)
// grid (128 m-tiles, KSPLIT), 256 threads, BK=64 stages, 3-stage ring.
// ---------------------------------------------------------------------------
template <int LAYER>
__global__ __launch_bounds__(256, 2)
void gemm_f16() {
    extern __shared__ char smem[];
    const uint32_t sb = s2u(smem);
    const int tid = threadIdx.x, lane = tid & 31, wid = tid >> 5;
    const int warp_m = wid >> 2, warp_n = wid & 3;
    const int m0 = blockIdx.x * 64;
    const int kb = blockIdx.y * KHALF;

    const __half* __restrict__ B = (LAYER == 1) ? g_B1 : g_B2;

    // ldmatrix lane offsets
    const uint32_t aLaneOff = (lane & 15) * PITCH + (lane >> 4) * 16;
    const uint32_t n16 = (lane & 7) + ((lane >> 4) << 3);
    const uint32_t bLaneOff = n16 * PITCH + ((lane >> 3) & 1) * 16;

    // cp.async assignments (16B chunks): per stage, per sub-tile:
    // A 1/thread, B 2/thread  -> 6 cp16 per thread per stage
    const int arow = tid >> 2, c16 = tid & 3;
    const __half* gA = g_Ah + (size_t)(m0 + arow) * NN + kb + c16 * 8;
    const uint32_t sAoff = AH_OFF + arow * PITCH + c16 * 16;
    const int brow0 = tid >> 2, brow1 = brow0 + 64;
    const __half* gB0 = B + (size_t)brow0 * NN + kb + c16 * 8;
    const __half* gB1 = B + (size_t)brow1 * NN + kb + c16 * 8;
    const uint32_t sBoff0 = BH_OFF + brow0 * PITCH + c16 * 16;
    const uint32_t sBoff1 = BH_OFF + brow1 * PITCH + c16 * 16;

    float am[2][4][4];
    #pragma unroll
    for (int i = 0; i < 2; ++i)
        #pragma unroll
        for (int j = 0; j < 4; ++j)
            #pragma unroll
            for (int q = 0; q < 4; ++q) am[i][j][q] = 0.0f;

    constexpr int NT = KHALF / 64;            // 64 stages

    // ---- prologue: issue stages 0..1 ----
    #pragma unroll
    for (int s = 0; s < NSTAGE - 1; ++s) {
        const uint32_t bb = sb + (uint32_t)s * BUF_BYTES;
        #pragma unroll
        for (int h = 0; h < 2; ++h) {
            const int kc = s * 64 + h * 32;
            const uint32_t hb = bb + (uint32_t)h * SUB_BYTES;
            cp16(hb + sAoff,  gA  + kc);
            cp16(hb + sBoff0, gB0 + kc);
            cp16(hb + sBoff1, gB1 + kc);
        }
        CP_COMMIT();
    }

    // ---- main loop: 64 stages of BK=64 ----
    #pragma unroll 1
    for (int t = 0; t < NT; ++t) {
        CP_WAIT1();            // stage t landed
        __syncthreads();       // all warps done reading recycled buffer

        const int tp = t + NSTAGE - 1;
        if (tp < NT) {
            const uint32_t bb = sb + (uint32_t)(tp % NSTAGE) * BUF_BYTES;
            #pragma unroll
            for (int h = 0; h < 2; ++h) {
                const int kc = tp * 64 + h * 32;
                const uint32_t hb = bb + (uint32_t)h * SUB_BYTES;
                cp16(hb + sAoff,  gA  + kc);
                cp16(hb + sBoff0, gB0 + kc);
                cp16(hb + sBoff1, gB1 + kc);
            }
        }
        CP_COMMIT();           // every stage (possibly empty group)

        const uint32_t bb = sb + (uint32_t)(t % NSTAGE) * BUF_BYTES;
        compute_sub(bb,             aLaneOff, bLaneOff, warp_m, warp_n, am);
        compute_sub(bb + SUB_BYTES, aLaneOff, bLaneOff, warp_m, warp_n, am);
    }

    // ---- store raw fp32 partial [m][n] ----
    float* dst = g_part + (size_t)blockIdx.y * NN * WID;
    const int r_base = warp_m * 32 + (lane >> 2);
    const int c_base = warp_n * 32 + (lane & 3) * 2;
    #pragma unroll
    for (int mt = 0; mt < 2; ++mt)
        #pragma unroll
        for (int nt = 0; nt < 4; ++nt) {
            int r = m0 + r_base + mt * 16;
            int c = c_base + nt * 8;
            *reinterpret_cast<float2*>(&dst[(size_t)r * WID + c]) =
                make_float2(am[mt][nt][0], am[mt][nt][1]);
            *reinterpret_cast<float2*>(&dst[(size_t)(r + 8) * WID + c]) =
                make_float2(am[mt][nt][2], am[mt][nt][3]);
        }
}

// ---------------------------------------------------------------------------
// reduce_l1: g_B2[n][k] = f16( relu_{n<64}( (p0+p1)[k][n] / 8192 ) )
// ---------------------------------------------------------------------------
__global__ void reduce_l1() {
    __shared__ float tile[32][33];
    int k0 = blockIdx.x * 32, n0 = blockIdx.y * 32;
    int tx = threadIdx.x, ty = threadIdx.y;
    const float* p0 = g_part;
    const float* p1 = g_part + (size_t)NN * WID;
    #pragma unroll
    for (int j = 0; j < 4; ++j) {
        int r = ty + 8 * j;
        size_t o = (size_t)(k0 + r) * WID + n0 + tx;
        float v = (p0[o] + p1[o]) * (1.0f / 8192.0f);
        if (n0 + tx < 64) v = fmaxf(v, 0.0f);
        tile[r][tx] = v;
    }
    __syncthreads();
    #pragma unroll
    for (int j = 0; j < 4; ++j) {
        int rn = ty + 8 * j;
        g_B2[(size_t)(n0 + rn) * NN + k0 + tx] = __float2half_rn(tile[tx][rn]);
    }
}

// ---------------------------------------------------------------------------
// reduce_l2: out[m][n] = relu_{n<64}( (p0+p1)/8192 )
// ---------------------------------------------------------------------------
__global__ __launch_bounds__(256) void reduce_l2(float* __restrict__ outp) {
    size_t i4 = (size_t)blockIdx.x * 256 + threadIdx.x;
    const float4* p0 = reinterpret_cast<const float4*>(g_part);
    const float4* p1 = reinterpret_cast<const float4*>(g_part + (size_t)NN * WID);
    float4 a = p0[i4], b = p1[i4];
    float4 v = make_float4((a.x + b.x) * (1.0f / 8192.0f),
                           (a.y + b.y) * (1.0f / 8192.0f),
                           (a.z + b.z) * (1.0f / 8192.0f),
                           (a.w + b.w) * (1.0f / 8192.0f));
    if (((i4 * 4) & 127) < 64) {
        v.x = fmaxf(v.x, 0.0f); v.y = fmaxf(v.y, 0.0f);
        v.z = fmaxf(v.z, 0.0f); v.w = fmaxf(v.w, 0.0f);
    }
    reinterpret_cast<float4*>(outp)[i4] = v;
}

// ---------------------------------------------------------------------------
// launch chain. Graph-capturable, allocation-free, deterministic.
// ---------------------------------------------------------------------------
extern "C" void kernel_launch(void* const* d_in, const int* in_sizes, int n_in,
                              void* d_out, int out_size) {
    const float* A  = (const float*)d_in[0];
    const float* F  = (const float*)d_in[1];
    const float* NF = (const float*)d_in[2];
    float* out = (float*)d_out;

    cudaFuncSetAttribute(gemm_f16<1>, cudaFuncAttributeMaxDynamicSharedMemorySize, SMEM_GEMM);
    cudaFuncSetAttribute(gemm_f16<2>, cudaFuncAttributeMaxDynamicSharedMemorySize, SMEM_GEMM);

    conv_a<<<(int)((size_t)NN * NN / 8 / 256), 256>>>(A);
    conv_b1<<<dim3(NN / 32, WID / 32), dim3(32, 8)>>>(F, NF);
    gemm_f16<1><<<dim3(NN / 64, KSPLIT), 256, SMEM_GEMM>>>();
    reduce_l1<<<dim3(NN / 32, WID / 32), dim3(32, 8)>>>();
    gemm_f16<2><<<dim3(NN / 64, KSPLIT), 256, SMEM_GEMM>>>();
    reduce_l2<<<(NN * WID / 4) / 256, 256>>>(out);
}